// round 14
// baseline (speedup 1.0000x reference)
#include <cuda_runtime.h>
#include <cuda_fp16.h>
#include <math.h>
#include <stdint.h>

#define NN 100000
#define EPS 1e-5f
#define NBLK 98   // ceil(NN/1024)

// ---------------- scratch (static device globals) ----------------------------
__device__ int    g_deg[NN];
__device__ int    g_off[NN + 1];
__device__ int    g_cur[NN];
__device__ int    g_bsum[NBLK];
__device__ int    g_csr[3200000];
__device__ float  g_norm[NN];
__device__ unsigned g_cnt[2];
__device__ __align__(128) __half g_h0[NN * 128];    // x*norm, half
__device__ __align__(128) __half g_agg1[NN * 128];  // gathered, *norm_dst
__device__ __align__(128) __half g_z1[NN * 256];
__device__ __align__(128) __half g_h1[NN * 256];    // relu(bn(z1))*norm
__device__ __align__(128) __half g_agg2[NN * 256];
__device__ __align__(128) __half g_z2[NN * 256];
__device__ __align__(128) __half g_h2[NN * 256];    // relu(bn(z2))*norm
__device__ __align__(128) __half g_xp[NN * 40];     // h2 @ W3 (src-scaled)
__device__ double g_stats[4 * 256];
__device__ float  g_bnp[4 * 256];
__device__ __align__(128) __half g_w1[256 * 128];   // W1^T [N=256][K=128]
__device__ __align__(128) __half g_w2[256 * 256];   // W2^T
__device__ __align__(128) __half g_w3[40 * 256];    // W3^T [N=40][K=256]

// ---------------- smem addr / ldmatrix / mma helpers --------------------------
__device__ __forceinline__ uint32_t smem_u32(const void* p) {
    uint32_t a;
    asm("{ .reg .u64 t; cvta.to.shared.u64 t, %1; cvt.u32.u64 %0, t; }"
        : "=r"(a) : "l"(p));
    return a;
}

__device__ __forceinline__ void ldsm4(uint32_t* r, uint32_t addr) {
    asm volatile("ldmatrix.sync.aligned.m8n8.x4.shared.b16 {%0,%1,%2,%3}, [%4];"
                 : "=r"(r[0]), "=r"(r[1]), "=r"(r[2]), "=r"(r[3]) : "r"(addr));
}

__device__ __forceinline__ void mma16816(float* d, const uint32_t* a,
                                         const uint32_t* b, const float* c) {
    asm volatile(
        "mma.sync.aligned.m16n8k16.row.col.f32.f16.f16.f32 "
        "{%0,%1,%2,%3}, {%4,%5,%6,%7}, {%8,%9}, {%10,%11,%12,%13};"
        : "=f"(d[0]), "=f"(d[1]), "=f"(d[2]), "=f"(d[3])
        : "r"(a[0]), "r"(a[1]), "r"(a[2]), "r"(a[3]),
          "r"(b[0]), "r"(b[1]),
          "f"(c[0]), "f"(c[1]), "f"(c[2]), "f"(c[3]));
}

// ---------------- CSR build ---------------------------------------------------
__global__ void k_hist(const int* __restrict__ dst, int E) {
    int i = blockIdx.x * blockDim.x + threadIdx.x;
    int e = i * 2;
    if (e + 1 < E) {
        int2 d = __ldg((const int2*)dst + i);
        atomicAdd(&g_deg[d.x], 1);
        atomicAdd(&g_deg[d.y], 1);
    } else if (e < E) {
        atomicAdd(&g_deg[__ldg(dst + e)], 1);
    }
}

// phase A: per-1024-block sums
__global__ void k_scan_a() {
    __shared__ int sh[32];
    int i = blockIdx.x * 1024 + threadIdx.x;
    int v = (i < NN) ? g_deg[i] : 0;
    #pragma unroll
    for (int o = 16; o; o >>= 1) v += __shfl_xor_sync(0xffffffffu, v, o);
    if ((threadIdx.x & 31) == 0) sh[threadIdx.x >> 5] = v;
    __syncthreads();
    if (threadIdx.x < 32) {
        int u = sh[threadIdx.x];
        #pragma unroll
        for (int o = 16; o; o >>= 1) u += __shfl_xor_sync(0xffffffffu, u, o);
        if (threadIdx.x == 0) g_bsum[blockIdx.x] = u;
    }
}

// phase C: each block redundantly scans block sums, then local scan + base.
__global__ void k_scan_c() {
    __shared__ int sh[1024];
    __shared__ int bs[128];
    int tid = threadIdx.x;
    if (tid < 128) bs[tid] = (tid < NBLK) ? g_bsum[tid] : 0;
    __syncthreads();
    for (int o = 1; o < 128; o <<= 1) {
        int u = (tid < 128 && tid >= o) ? bs[tid - o] : 0;
        __syncthreads();
        if (tid < 128) bs[tid] += u;
        __syncthreads();
    }
    int i = blockIdx.x * 1024 + tid;
    int v = (i < NN) ? g_deg[i] : 0;
    sh[tid] = v;
    __syncthreads();
    for (int o = 1; o < 1024; o <<= 1) {
        int u = (tid >= o) ? sh[tid - o] : 0;
        __syncthreads();
        sh[tid] += u;
        __syncthreads();
    }
    if (i < NN) {
        int base = blockIdx.x ? bs[blockIdx.x - 1] : 0;
        int ex = sh[tid] - v + base;
        g_off[i] = ex;
        g_cur[i] = ex;
        g_norm[i] = rsqrtf(fmaxf((float)v, 1.0f));
    }
    if (blockIdx.x == 0 && tid == 0) g_off[NN] = bs[NBLK - 1];
}

__global__ void k_fill(const int* __restrict__ src, const int* __restrict__ dst, int E) {
    int i = blockIdx.x * blockDim.x + threadIdx.x;
    int e = i * 2;
    if (e + 1 < E) {
        int2 d = __ldg((const int2*)dst + i);
        int2 s = __ldg((const int2*)src + i);
        g_csr[atomicAdd(&g_cur[d.x], 1)] = s.x;
        g_csr[atomicAdd(&g_cur[d.y], 1)] = s.y;
    } else if (e < E) {
        g_csr[atomicAdd(&g_cur[__ldg(dst + e)], 1)] = __ldg(src + e);
    }
}

// ---------------- W transpose+convert (fused, all 3) --------------------------
__global__ void k_wconv_all(const float* __restrict__ W1, const float* __restrict__ W2,
                            const float* __restrict__ W3) {
    int i = blockIdx.x * 256 + threadIdx.x;
    if (i < 32768) {                       // g_w1[n*128+k] = W1[k*256+n]
        int n = i >> 7, k = i & 127;
        g_w1[i] = __float2half(__ldg(W1 + k * 256 + n));
    } else if (i < 98304) {                // g_w2[n*256+k] = W2[k*256+n]
        int j = i - 32768;
        int n = j >> 8, k = j & 255;
        g_w2[j] = __float2half(__ldg(W2 + k * 256 + n));
    } else if (i < 108544) {               // g_w3[n*256+k] = W3[k*40+n]
        int j = i - 98304;
        int n = j >> 8, k = j & 255;
        g_w3[j] = __float2half(__ldg(W3 + k * 40 + n));
    }
}

// ---------------- feature prep ------------------------------------------------
__global__ void k_prep0(const float* __restrict__ x) {
    int t = blockIdx.x * blockDim.x + threadIdx.x;
    if (t >= NN * 64) return;
    int row = t >> 6;
    float n = g_norm[row];
    float2 v = __ldcs((const float2*)x + t);
    ((__half2*)g_h0)[t] = __floats2half2_rn(v.x * n, v.y * n);
}

// z(half) -> h(half) = relu(z*sc+sh)*norm
__global__ void k_prep(const __half* __restrict__ Zl, const float* __restrict__ sc,
                       const float* __restrict__ sh, __half* __restrict__ Hh) {
    int t = blockIdx.x * blockDim.x + threadIdx.x;
    if (t >= NN * 128) return;
    int row = t >> 7, c2 = t & 127;
    float n = g_norm[row];
    float2 zf = __half22float2(__ldcs((const __half2*)Zl + t));
    float2 s2 = ((const float2*)sc)[c2];
    float2 h2 = ((const float2*)sh)[c2];
    float a = fmaxf(fmaf(zf.x, s2.x, h2.x), 0.f) * n;
    float b = fmaxf(fmaf(zf.y, s2.y, h2.y), 0.f) * n;
    ((__half2*)Hh)[t] = __floats2half2_rn(a, b);
}

// ---------------- CSR gathers (direct idx loads, unroll 8, NPW nodes/group) ---
__device__ __forceinline__ void add8(float* a, uint4 u) {
    __half2* h = (__half2*)&u;
    #pragma unroll
    for (int i = 0; i < 4; i++) {
        float2 f = __half22float2(h[i]);
        a[2 * i] += f.x;
        a[2 * i + 1] += f.y;
    }
}

template <int FEAT, int NPW>
__global__ void k_gather(const __half* __restrict__ H, __half* __restrict__ OUT) {
    const int G = FEAT / 8;  // threads per node, 16B each
    int grp = blockIdx.x * (256 / G) + threadIdx.x / G;
    int t = threadIdx.x % G;
    int node0 = grp * NPW;
    const uint4* Hv = reinterpret_cast<const uint4*>(H);
    int nend = min(node0 + NPW, NN);
    for (int node = node0; node < nend; node++) {
        int beg = g_off[node], end = g_off[node + 1];
        float acc[8] = {0, 0, 0, 0, 0, 0, 0, 0};
        int j = beg;
        for (; j + 8 <= end; j += 8) {
            int s[8];
            #pragma unroll
            for (int u = 0; u < 8; u++) s[u] = __ldg(g_csr + j + u);
            uint4 v[8];
            #pragma unroll
            for (int u = 0; u < 8; u++) v[u] = __ldg(Hv + (size_t)s[u] * G + t);
            #pragma unroll
            for (int u = 0; u < 8; u++) add8(acc, v[u]);
        }
        for (; j < end; j++) {
            int s = __ldg(g_csr + j);
            add8(acc, __ldg(Hv + (size_t)s * G + t));
        }
        float nd = g_norm[node];
        __half2 o[4];
        #pragma unroll
        for (int i = 0; i < 4; i++)
            o[i] = __floats2half2_rn(acc[2 * i] * nd, acc[2 * i + 1] * nd);
        __stcs(reinterpret_cast<float4*>(OUT) + (size_t)node * G + t, *(float4*)o);
    }
}

// layer3 gather + log_softmax fused. 8 threads/node, t<5 hold 8 feats each.
__global__ void k_gather3_final(const float* __restrict__ b3, float* __restrict__ out) {
    int node = blockIdx.x * 32 + threadIdx.x / 8;
    int t = threadIdx.x & 7;
    int lane = threadIdx.x & 31;
    unsigned mask = 0xffu << (lane & ~7);
    if (node >= NN) return;
    float acc[8] = {0, 0, 0, 0, 0, 0, 0, 0};
    if (t < 5) {
        int beg = g_off[node], end = g_off[node + 1];
        const uint4* Hv = reinterpret_cast<const uint4*>(g_xp);  // 5 uint4/row
        int j = beg;
        for (; j + 8 <= end; j += 8) {
            int s[8];
            #pragma unroll
            for (int u = 0; u < 8; u++) s[u] = __ldg(g_csr + j + u);
            uint4 v[8];
            #pragma unroll
            for (int u = 0; u < 8; u++) v[u] = __ldg(Hv + (size_t)s[u] * 5 + t);
            #pragma unroll
            for (int u = 0; u < 8; u++) add8(acc, v[u]);
        }
        for (; j < end; j++) {
            int s = __ldg(g_csr + j);
            add8(acc, __ldg(Hv + (size_t)s * 5 + t));
        }
    }
    float nrm = g_norm[node];
    float v[8];
    float lm = -1e30f;
    if (t < 5) {
        #pragma unroll
        for (int i = 0; i < 8; i++) {
            v[i] = acc[i] * nrm + __ldg(b3 + t * 8 + i);
            lm = fmaxf(lm, v[i]);
        }
    }
    #pragma unroll
    for (int o = 4; o; o >>= 1) lm = fmaxf(lm, __shfl_xor_sync(mask, lm, o));
    float ls = 0.f;
    if (t < 5) {
        #pragma unroll
        for (int i = 0; i < 8; i++) ls += __expf(v[i] - lm);
    }
    #pragma unroll
    for (int o = 4; o; o >>= 1) ls += __shfl_xor_sync(mask, ls, o);
    float lg = __logf(ls);
    if (t < 5) {
        float4 o0 = {v[0] - lm - lg, v[1] - lm - lg, v[2] - lm - lg, v[3] - lm - lg};
        float4 o1 = {v[4] - lm - lg, v[5] - lm - lg, v[6] - lm - lg, v[7] - lm - lg};
        float* op = out + (size_t)node * 40 + t * 8;
        *(float4*)op = o0;
        *(float4*)(op + 4) = o1;
    }
}

// ---------------- HMMA GEMM: Z[M,N_] = half(A[M,K_] @ Bt[N_,K_]^T + bias) ----
// CTA 128x64, 8 warps (4M x 2N), warp 32x32, mma.sync m16n8k16 f16->f32.
template <int N_, int K_, bool HAS_BIAS>
__global__ void __launch_bounds__(256) k_gemm_mma(
    const __half* __restrict__ A, const float* __restrict__ bias,
    const __half* __restrict__ Bh, __half* __restrict__ Z, int M) {
    constexpr int KA = K_ + 8;  // halfs per smem row (16B pad, conflict-free ldsm)
    extern __shared__ __half sm[];
    __half* Asm = sm;                 // [128][KA]
    __half* Bsm = sm + 128 * KA;      // [64][KA]

    int tid = threadIdx.x;
    int wid = tid >> 5, lane = tid & 31;
    int m0 = blockIdx.x * 128, n0 = blockIdx.y * 64;

    // load A tile (zeros past M); A is a single-use stream -> evict-first
    const uint4* Ag = (const uint4*)A;
    for (int i = tid; i < 128 * (K_ / 8); i += 256) {
        int r = i / (K_ / 8), u = i % (K_ / 8);
        uint4 v = make_uint4(0, 0, 0, 0);
        if (m0 + r < M) v = __ldcs(Ag + (size_t)(m0 + r) * (K_ / 8) + u);
        *(uint4*)(Asm + r * KA + u * 8) = v;
    }
    // load B tile (zeros past N_); W is hot -> default caching
    const uint4* Bg = (const uint4*)Bh;
    for (int i = tid; i < 64 * (K_ / 8); i += 256) {
        int r = i / (K_ / 8), u = i % (K_ / 8);
        uint4 v = make_uint4(0, 0, 0, 0);
        if (n0 + r < N_) v = __ldg(Bg + (size_t)(n0 + r) * (K_ / 8) + u);
        *(uint4*)(Bsm + r * KA + u * 8) = v;
    }
    __syncthreads();

    int wm = wid & 3, wn = wid >> 2;
    uint32_t a_base = smem_u32(Asm);
    uint32_t b_base = smem_u32(Bsm);

    float acc[2][4][4] = {};

    int arow = wm * 32 + (lane & 15);
    int acol = (lane >> 4) * 8;
    int brow = wn * 32 + ((lane >> 4) ? 8 : 0) + (lane & 7);
    int bk = ((lane >> 3) & 1) * 8;

    #pragma unroll 4
    for (int k0 = 0; k0 < K_; k0 += 16) {
        uint32_t a[2][4];
        #pragma unroll
        for (int mi = 0; mi < 2; mi++)
            ldsm4(a[mi], a_base + (uint32_t)(((arow + mi * 16) * KA + k0 + acol) * 2));
        uint32_t b[2][4];
        #pragma unroll
        for (int nq = 0; nq < 2; nq++)
            ldsm4(b[nq], b_base + (uint32_t)(((brow + nq * 16) * KA + k0 + bk) * 2));
        #pragma unroll
        for (int mi = 0; mi < 2; mi++)
            #pragma unroll
            for (int ni = 0; ni < 4; ni++)
                mma16816(acc[mi][ni], a[mi], &b[ni >> 1][(ni & 1) * 2], acc[mi][ni]);
    }

    int cbase = n0 + wn * 32 + (lane & 3) * 2;
    #pragma unroll
    for (int mi = 0; mi < 2; mi++) {
        int rowt = m0 + wm * 32 + mi * 16 + (lane >> 2);
        #pragma unroll
        for (int hrow = 0; hrow < 2; hrow++) {
            int rr = rowt + hrow * 8;
            if (rr >= M) continue;
            #pragma unroll
            for (int ni = 0; ni < 4; ni++) {
                int col = cbase + ni * 8;
                if ((N_ % 64 == 0) || (col + 1 < N_)) {
                    float v0 = acc[mi][ni][hrow * 2 + 0];
                    float v1 = acc[mi][ni][hrow * 2 + 1];
                    if (HAS_BIAS) {
                        v0 += __ldg(bias + col);
                        v1 += __ldg(bias + col + 1);
                    }
                    *(__half2*)(Z + (size_t)rr * N_ + col) = __floats2half2_rn(v0, v1);
                }
            }
        }
    }
}

// ---------------- BN column stats + fused finalize (last-block pattern) -------
__global__ void k_colstats(const __half* __restrict__ Zl, double* __restrict__ sum,
                           double* __restrict__ sq, int M,
                           const float* __restrict__ gamma,
                           const float* __restrict__ beta,
                           float* __restrict__ scale, float* __restrict__ shift,
                           unsigned* __restrict__ cnt) {
    int c2 = threadIdx.x;  // 128 threads = 128 half2 column pairs
    int r0 = blockIdx.x * 512;
    int rend = min(r0 + 512, M);
    float s0 = 0.f, s1 = 0.f, q0 = 0.f, q1 = 0.f;
    const __half2* Z2 = (const __half2*)Zl;
    for (int r = r0; r < rend; r++) {
        float2 v = __half22float2(__ldg(Z2 + (size_t)r * 128 + c2));
        s0 += v.x;
        s1 += v.y;
        q0 = fmaf(v.x, v.x, q0);
        q1 = fmaf(v.y, v.y, q1);
    }
    atomicAdd(&sum[c2 * 2 + 0], (double)s0);
    atomicAdd(&sum[c2 * 2 + 1], (double)s1);
    atomicAdd(&sq[c2 * 2 + 0], (double)q0);
    atomicAdd(&sq[c2 * 2 + 1], (double)q1);

    __threadfence();
    __shared__ bool last;
    if (threadIdx.x == 0)
        last = (atomicAdd(cnt, 1u) == gridDim.x - 1);
    __syncthreads();
    if (last) {
        for (int i = threadIdx.x; i < 256; i += 128) {
            double mean = sum[i] / (double)NN;
            double var = sq[i] / (double)NN - mean * mean;
            float rstd = (float)(1.0 / sqrt(var + (double)EPS));
            float sc = rstd * __ldg(gamma + i);
            scale[i] = sc;
            shift[i] = __ldg(beta + i) - (float)mean * sc;
        }
    }
}

// ---------------- launch -----------------------------------------------------
extern "C" void kernel_launch(void* const* d_in, const int* in_sizes, int n_in,
                              void* d_out, int out_size) {
    const float* x      = (const float*)d_in[0];
    const int*   src    = (const int*)  d_in[1];
    const int*   dst    = (const int*)  d_in[2];
    const float* W1     = (const float*)d_in[3];
    const float* b1     = (const float*)d_in[4];
    const float* gamma1 = (const float*)d_in[5];
    const float* beta1  = (const float*)d_in[6];
    const float* W2     = (const float*)d_in[7];
    const float* b2     = (const float*)d_in[8];
    const float* gamma2 = (const float*)d_in[9];
    const float* beta2  = (const float*)d_in[10];
    const float* W3     = (const float*)d_in[11];
    const float* b3     = (const float*)d_in[12];
    float* out = (float*)d_out;
    int E = in_sizes[1];

    void *p_deg, *p_stats, *p_bnp, *p_h0, *p_h1, *p_h2, *p_cnt;
    void *p_agg1, *p_z1, *p_agg2, *p_z2, *p_xp;
    void *p_w1, *p_w2, *p_w3;
    cudaGetSymbolAddress(&p_deg,   g_deg);
    cudaGetSymbolAddress(&p_stats, g_stats);
    cudaGetSymbolAddress(&p_bnp,   g_bnp);
    cudaGetSymbolAddress(&p_h0,    g_h0);
    cudaGetSymbolAddress(&p_h1,    g_h1);
    cudaGetSymbolAddress(&p_h2,    g_h2);
    cudaGetSymbolAddress(&p_cnt,   g_cnt);
    cudaGetSymbolAddress(&p_agg1,  g_agg1);
    cudaGetSymbolAddress(&p_z1,    g_z1);
    cudaGetSymbolAddress(&p_agg2,  g_agg2);
    cudaGetSymbolAddress(&p_z2,    g_z2);
    cudaGetSymbolAddress(&p_xp,    g_xp);
    cudaGetSymbolAddress(&p_w1,    g_w1);
    cudaGetSymbolAddress(&p_w2,    g_w2);
    cudaGetSymbolAddress(&p_w3,    g_w3);

    const int SM1 = 192 * (128 + 8) * 2;  // 52224
    const int SM2 = 192 * (256 + 8) * 2;  // 101376
    const int SM3 = SM2;
    cudaFuncSetAttribute(k_gemm_mma<256, 128, true>,
                         cudaFuncAttributeMaxDynamicSharedMemorySize, SM1);
    cudaFuncSetAttribute(k_gemm_mma<256, 256, true>,
                         cudaFuncAttributeMaxDynamicSharedMemorySize, SM2);
    cudaFuncSetAttribute(k_gemm_mma<40, 256, false>,
                         cudaFuncAttributeMaxDynamicSharedMemorySize, SM3);

    cudaMemsetAsync(p_deg, 0, NN * sizeof(int), 0);
    cudaMemsetAsync(p_stats, 0, 4 * 256 * sizeof(double), 0);
    cudaMemsetAsync(p_cnt, 0, 2 * sizeof(unsigned), 0);

    const int T = 256;
    double* st = (double*)p_stats;
    float* bnp = (float*)p_bnp;
    unsigned* cnt = (unsigned*)p_cnt;
    int mg = (NN + 127) / 128;  // 782
    int csblk = (NN + 511) / 512;

    // W conversions (fused)
    k_wconv_all<<<(108544 + T - 1) / T, T>>>(W1, W2, W3);

    // CSR build + norms (norm fused into scan_c)
    k_hist<<<(E / 2 + T - 1) / T, T>>>(dst, E);
    k_scan_a<<<NBLK, 1024>>>();
    k_scan_c<<<NBLK, 1024>>>();
    k_fill<<<(E / 2 + T - 1) / T, T>>>(src, dst, E);

    // layer 1 (gathers: 4 nodes per group for degree balance)
    k_prep0<<<(NN * 64 + T - 1) / T, T>>>(x);
    k_gather<128, 4><<<(NN + 63) / 64, T>>>((const __half*)p_h0, (__half*)p_agg1);
    k_gemm_mma<256, 128, true><<<dim3(mg, 4), T, SM1>>>(
        (const __half*)p_agg1, b1, (const __half*)p_w1, (__half*)p_z1, NN);
    k_colstats<<<csblk, 128>>>((const __half*)p_z1, st, st + 256, NN,
                               gamma1, beta1, bnp, bnp + 256, cnt);
    k_prep<<<(NN * 128 + T - 1) / T, T>>>((const __half*)p_z1, bnp, bnp + 256,
                                          (__half*)p_h1);

    // layer 2
    k_gather<256, 4><<<(NN + 31) / 32, T>>>((const __half*)p_h1, (__half*)p_agg2);
    k_gemm_mma<256, 256, true><<<dim3(mg, 4), T, SM2>>>(
        (const __half*)p_agg2, b2, (const __half*)p_w2, (__half*)p_z2, NN);
    k_colstats<<<csblk, 128>>>((const __half*)p_z2, st + 512, st + 768, NN,
                               gamma2, beta2, bnp + 512, bnp + 768, cnt + 1);
    k_prep<<<(NN * 128 + T - 1) / T, T>>>((const __half*)p_z2, bnp + 512, bnp + 768,
                                          (__half*)p_h2);

    // layer 3: xp = h2 @ W3 (src-scaled), fused gather+log_softmax
    k_gemm_mma<40, 256, false><<<dim3(mg, 1), T, SM3>>>(
        (const __half*)p_h2, nullptr, (const __half*)p_w3, (__half*)p_xp, NN);
    k_gather3_final<<<(NN + 31) / 32, T>>>(b3, out);
}

// round 15
// speedup vs baseline: 1.1617x; 1.1617x over previous
#include <cuda_runtime.h>
#include <cuda_fp16.h>
#include <math.h>
#include <stdint.h>

#define NN 100000
#define EPS 1e-5f
#define NBLK 98   // ceil(NN/1024)

// ---------------- scratch (static device globals) ----------------------------
__device__ int    g_deg[NN];
__device__ int    g_off[NN + 1];
__device__ int    g_cur[NN];
__device__ int    g_bsum[NBLK];
__device__ int    g_csr[3200000];
__device__ float  g_norm[NN];
__device__ unsigned g_cnt[2];
__device__ __align__(128) __half g_h0[NN * 128];    // x*norm, half
__device__ __align__(128) __half g_agg1[NN * 128];  // gathered, *norm_dst
__device__ __align__(128) __half g_z1[NN * 256];
__device__ __align__(128) __half g_h1[NN * 256];    // relu(bn(z1))*norm
__device__ __align__(128) __half g_agg2[NN * 256];
__device__ __align__(128) __half g_z2[NN * 256];
__device__ __align__(128) __half g_h2[NN * 256];    // relu(bn(z2))*norm
__device__ __align__(128) __half g_xp[NN * 40];     // h2 @ W3 (src-scaled)
__device__ double g_stats[4 * 256];
__device__ float  g_bnp[4 * 256];
__device__ __align__(128) __half g_w1[256 * 128];   // W1^T [N=256][K=128]
__device__ __align__(128) __half g_w2[256 * 256];   // W2^T
__device__ __align__(128) __half g_w3[40 * 256];    // W3^T [N=40][K=256]

// ---------------- smem addr / ldmatrix / mma helpers --------------------------
__device__ __forceinline__ uint32_t smem_u32(const void* p) {
    uint32_t a;
    asm("{ .reg .u64 t; cvta.to.shared.u64 t, %1; cvt.u32.u64 %0, t; }"
        : "=r"(a) : "l"(p));
    return a;
}

__device__ __forceinline__ void ldsm4(uint32_t* r, uint32_t addr) {
    asm volatile("ldmatrix.sync.aligned.m8n8.x4.shared.b16 {%0,%1,%2,%3}, [%4];"
                 : "=r"(r[0]), "=r"(r[1]), "=r"(r[2]), "=r"(r[3]) : "r"(addr));
}

__device__ __forceinline__ void mma16816(float* d, const uint32_t* a,
                                         const uint32_t* b, const float* c) {
    asm volatile(
        "mma.sync.aligned.m16n8k16.row.col.f32.f16.f16.f32 "
        "{%0,%1,%2,%3}, {%4,%5,%6,%7}, {%8,%9}, {%10,%11,%12,%13};"
        : "=f"(d[0]), "=f"(d[1]), "=f"(d[2]), "=f"(d[3])
        : "r"(a[0]), "r"(a[1]), "r"(a[2]), "r"(a[3]),
          "r"(b[0]), "r"(b[1]),
          "f"(c[0]), "f"(c[1]), "f"(c[2]), "f"(c[3]));
}

// ---------------- CSR build ---------------------------------------------------
__global__ void k_hist(const int* __restrict__ dst, int E) {
    int i = blockIdx.x * blockDim.x + threadIdx.x;
    int e = i * 2;
    if (e + 1 < E) {
        int2 d = __ldg((const int2*)dst + i);
        atomicAdd(&g_deg[d.x], 1);
        atomicAdd(&g_deg[d.y], 1);
    } else if (e < E) {
        atomicAdd(&g_deg[__ldg(dst + e)], 1);
    }
}

// phase A: per-1024-block sums
__global__ void k_scan_a() {
    __shared__ int sh[32];
    int i = blockIdx.x * 1024 + threadIdx.x;
    int v = (i < NN) ? g_deg[i] : 0;
    #pragma unroll
    for (int o = 16; o; o >>= 1) v += __shfl_xor_sync(0xffffffffu, v, o);
    if ((threadIdx.x & 31) == 0) sh[threadIdx.x >> 5] = v;
    __syncthreads();
    if (threadIdx.x < 32) {
        int u = sh[threadIdx.x];
        #pragma unroll
        for (int o = 16; o; o >>= 1) u += __shfl_xor_sync(0xffffffffu, u, o);
        if (threadIdx.x == 0) g_bsum[blockIdx.x] = u;
    }
}

// phase C: each block redundantly scans block sums, then local scan + base.
__global__ void k_scan_c() {
    __shared__ int sh[1024];
    __shared__ int bs[128];
    int tid = threadIdx.x;
    if (tid < 128) bs[tid] = (tid < NBLK) ? g_bsum[tid] : 0;
    __syncthreads();
    for (int o = 1; o < 128; o <<= 1) {
        int u = (tid < 128 && tid >= o) ? bs[tid - o] : 0;
        __syncthreads();
        if (tid < 128) bs[tid] += u;
        __syncthreads();
    }
    int i = blockIdx.x * 1024 + tid;
    int v = (i < NN) ? g_deg[i] : 0;
    sh[tid] = v;
    __syncthreads();
    for (int o = 1; o < 1024; o <<= 1) {
        int u = (tid >= o) ? sh[tid - o] : 0;
        __syncthreads();
        sh[tid] += u;
        __syncthreads();
    }
    if (i < NN) {
        int base = blockIdx.x ? bs[blockIdx.x - 1] : 0;
        int ex = sh[tid] - v + base;
        g_off[i] = ex;
        g_cur[i] = ex;
        g_norm[i] = rsqrtf(fmaxf((float)v, 1.0f));
    }
    if (blockIdx.x == 0 && tid == 0) g_off[NN] = bs[NBLK - 1];
}

__global__ void k_fill(const int* __restrict__ src, const int* __restrict__ dst, int E) {
    int i = blockIdx.x * blockDim.x + threadIdx.x;
    int e = i * 2;
    if (e + 1 < E) {
        int2 d = __ldg((const int2*)dst + i);
        int2 s = __ldg((const int2*)src + i);
        g_csr[atomicAdd(&g_cur[d.x], 1)] = s.x;
        g_csr[atomicAdd(&g_cur[d.y], 1)] = s.y;
    } else if (e < E) {
        g_csr[atomicAdd(&g_cur[__ldg(dst + e)], 1)] = __ldg(src + e);
    }
}

// ---------------- W transpose+convert (fused, all 3) --------------------------
__global__ void k_wconv_all(const float* __restrict__ W1, const float* __restrict__ W2,
                            const float* __restrict__ W3) {
    int i = blockIdx.x * 256 + threadIdx.x;
    if (i < 32768) {                       // g_w1[n*128+k] = W1[k*256+n]
        int n = i >> 7, k = i & 127;
        g_w1[i] = __float2half(__ldg(W1 + k * 256 + n));
    } else if (i < 98304) {                // g_w2[n*256+k] = W2[k*256+n]
        int j = i - 32768;
        int n = j >> 8, k = j & 255;
        g_w2[j] = __float2half(__ldg(W2 + k * 256 + n));
    } else if (i < 108544) {               // g_w3[n*256+k] = W3[k*40+n]
        int j = i - 98304;
        int n = j >> 8, k = j & 255;
        g_w3[j] = __float2half(__ldg(W3 + k * 40 + n));
    }
}

// ---------------- feature prep ------------------------------------------------
__global__ void k_prep0(const float* __restrict__ x) {
    int t = blockIdx.x * blockDim.x + threadIdx.x;
    if (t >= NN * 64) return;
    int row = t >> 6;
    float n = g_norm[row];
    float2 v = __ldcs((const float2*)x + t);
    ((__half2*)g_h0)[t] = __floats2half2_rn(v.x * n, v.y * n);
}

// z(half) -> h(half) = relu(z*sc+sh)*norm
__global__ void k_prep(const __half* __restrict__ Zl, const float* __restrict__ sc,
                       const float* __restrict__ sh, __half* __restrict__ Hh) {
    int t = blockIdx.x * blockDim.x + threadIdx.x;
    if (t >= NN * 128) return;
    int row = t >> 7, c2 = t & 127;
    float n = g_norm[row];
    float2 zf = __half22float2(__ldcs((const __half2*)Zl + t));
    float2 s2 = ((const float2*)sc)[c2];
    float2 h2 = ((const float2*)sh)[c2];
    float a = fmaxf(fmaf(zf.x, s2.x, h2.x), 0.f) * n;
    float b = fmaxf(fmaf(zf.y, s2.y, h2.y), 0.f) * n;
    ((__half2*)Hh)[t] = __floats2half2_rn(a, b);
}

// ---------------- CSR gathers (round-7 form, untouched: the measured optimum) -
__device__ __forceinline__ void add8(float* a, uint4 u) {
    __half2* h = (__half2*)&u;
    #pragma unroll
    for (int i = 0; i < 4; i++) {
        float2 f = __half22float2(h[i]);
        a[2 * i] += f.x;
        a[2 * i + 1] += f.y;
    }
}

template <int FEAT>
__global__ void k_gather(const __half* __restrict__ H, __half* __restrict__ OUT) {
    const int G = FEAT / 8;  // threads per node, 16B each
    int node = blockIdx.x * (256 / G) + threadIdx.x / G;
    int t = threadIdx.x % G;
    if (node >= NN) return;
    int beg = g_off[node], end = g_off[node + 1];
    const uint4* Hv = reinterpret_cast<const uint4*>(H);
    float acc[8] = {0, 0, 0, 0, 0, 0, 0, 0};
    int j = beg;
    for (; j + 8 <= end; j += 8) {
        int s[8];
        #pragma unroll
        for (int u = 0; u < 8; u++) s[u] = __ldg(g_csr + j + u);
        uint4 v[8];
        #pragma unroll
        for (int u = 0; u < 8; u++) v[u] = __ldg(Hv + (size_t)s[u] * G + t);
        #pragma unroll
        for (int u = 0; u < 8; u++) add8(acc, v[u]);
    }
    for (; j < end; j++) {
        int s = __ldg(g_csr + j);
        add8(acc, __ldg(Hv + (size_t)s * G + t));
    }
    float nd = g_norm[node];
    __half2 o[4];
    #pragma unroll
    for (int i = 0; i < 4; i++)
        o[i] = __floats2half2_rn(acc[2 * i] * nd, acc[2 * i + 1] * nd);
    __stcs(reinterpret_cast<float4*>(OUT) + (size_t)node * G + t, *(float4*)o);
}

// layer3 gather + log_softmax fused. 8 threads/node, t<5 hold 8 feats each.
__global__ void k_gather3_final(const float* __restrict__ b3, float* __restrict__ out) {
    int node = blockIdx.x * 32 + threadIdx.x / 8;
    int t = threadIdx.x & 7;
    int lane = threadIdx.x & 31;
    unsigned mask = 0xffu << (lane & ~7);
    if (node >= NN) return;
    float acc[8] = {0, 0, 0, 0, 0, 0, 0, 0};
    if (t < 5) {
        int beg = g_off[node], end = g_off[node + 1];
        const uint4* Hv = reinterpret_cast<const uint4*>(g_xp);  // 5 uint4/row
        int j = beg;
        for (; j + 8 <= end; j += 8) {
            int s[8];
            #pragma unroll
            for (int u = 0; u < 8; u++) s[u] = __ldg(g_csr + j + u);
            uint4 v[8];
            #pragma unroll
            for (int u = 0; u < 8; u++) v[u] = __ldg(Hv + (size_t)s[u] * 5 + t);
            #pragma unroll
            for (int u = 0; u < 8; u++) add8(acc, v[u]);
        }
        for (; j < end; j++) {
            int s = __ldg(g_csr + j);
            add8(acc, __ldg(Hv + (size_t)s * 5 + t));
        }
    }
    float nrm = g_norm[node];
    float v[8];
    float lm = -1e30f;
    if (t < 5) {
        #pragma unroll
        for (int i = 0; i < 8; i++) {
            v[i] = acc[i] * nrm + __ldg(b3 + t * 8 + i);
            lm = fmaxf(lm, v[i]);
        }
    }
    #pragma unroll
    for (int o = 4; o; o >>= 1) lm = fmaxf(lm, __shfl_xor_sync(mask, lm, o));
    float ls = 0.f;
    if (t < 5) {
        #pragma unroll
        for (int i = 0; i < 8; i++) ls += __expf(v[i] - lm);
    }
    #pragma unroll
    for (int o = 4; o; o >>= 1) ls += __shfl_xor_sync(mask, ls, o);
    float lg = __logf(ls);
    if (t < 5) {
        float4 o0 = {v[0] - lm - lg, v[1] - lm - lg, v[2] - lm - lg, v[3] - lm - lg};
        float4 o1 = {v[4] - lm - lg, v[5] - lm - lg, v[6] - lm - lg, v[7] - lm - lg};
        float* op = out + (size_t)node * 40 + t * 8;
        *(float4*)op = o0;
        *(float4*)(op + 4) = o1;
    }
}

// ---------------- HMMA GEMM: Z[M,N_] = half(A[M,K_] @ Bt[N_,K_]^T + bias) ----
// CTA owns 128 rows x FULL N_: A tile loaded ONCE, loop over 64-wide N
// quarters reloading only the B quarter (saves 4x A re-read through L2).
// 8 warps (4M x 2N), warp 32x32 per quarter, mma.sync m16n8k16 f16->f32.
template <int N_, int K_, bool HAS_BIAS>
__global__ void __launch_bounds__(256) k_gemm_mma(
    const __half* __restrict__ A, const float* __restrict__ bias,
    const __half* __restrict__ Bh, __half* __restrict__ Z, int M) {
    constexpr int KA = K_ + 8;  // halfs per smem row (16B pad, conflict-free ldsm)
    constexpr int NQ = (N_ + 63) / 64;
    extern __shared__ __half sm[];
    __half* Asm = sm;                 // [128][KA]
    __half* Bsm = sm + 128 * KA;      // [64][KA]

    int tid = threadIdx.x;
    int wid = tid >> 5, lane = tid & 31;
    int m0 = blockIdx.x * 128;

    // load A tile once (zeros past M); single-use stream -> evict-first
    const uint4* Ag = (const uint4*)A;
    for (int i = tid; i < 128 * (K_ / 8); i += 256) {
        int r = i / (K_ / 8), u = i % (K_ / 8);
        uint4 v = make_uint4(0, 0, 0, 0);
        if (m0 + r < M) v = __ldcs(Ag + (size_t)(m0 + r) * (K_ / 8) + u);
        *(uint4*)(Asm + r * KA + u * 8) = v;
    }

    int wm = wid & 3, wn = wid >> 2;
    uint32_t a_base = smem_u32(Asm);
    uint32_t b_base = smem_u32(Bsm);

    int arow = wm * 32 + (lane & 15);
    int acol = (lane >> 4) * 8;
    int brow = wn * 32 + ((lane >> 4) ? 8 : 0) + (lane & 7);
    int bk = ((lane >> 3) & 1) * 8;
    int cb_off = wn * 32 + (lane & 3) * 2;

    const uint4* Bg = (const uint4*)Bh;

    #pragma unroll 1
    for (int nq = 0; nq < NQ; nq++) {
        int n0 = nq * 64;
        // load B quarter (zeros past N_); W is hot -> default caching
        for (int i = tid; i < 64 * (K_ / 8); i += 256) {
            int r = i / (K_ / 8), u = i % (K_ / 8);
            uint4 v = make_uint4(0, 0, 0, 0);
            if (n0 + r < N_) v = __ldg(Bg + (size_t)(n0 + r) * (K_ / 8) + u);
            *(uint4*)(Bsm + r * KA + u * 8) = v;
        }
        __syncthreads();

        float acc[2][4][4] = {};
        #pragma unroll 4
        for (int k0 = 0; k0 < K_; k0 += 16) {
            uint32_t a[2][4];
            #pragma unroll
            for (int mi = 0; mi < 2; mi++)
                ldsm4(a[mi], a_base + (uint32_t)(((arow + mi * 16) * KA + k0 + acol) * 2));
            uint32_t b[2][4];
            #pragma unroll
            for (int nqq = 0; nqq < 2; nqq++)
                ldsm4(b[nqq], b_base + (uint32_t)(((brow + nqq * 16) * KA + k0 + bk) * 2));
            #pragma unroll
            for (int mi = 0; mi < 2; mi++)
                #pragma unroll
                for (int ni = 0; ni < 4; ni++)
                    mma16816(acc[mi][ni], a[mi], &b[ni >> 1][(ni & 1) * 2], acc[mi][ni]);
        }

        // epilogue for this quarter
        int cbase = n0 + cb_off;
        #pragma unroll
        for (int mi = 0; mi < 2; mi++) {
            int rowt = m0 + wm * 32 + mi * 16 + (lane >> 2);
            #pragma unroll
            for (int hrow = 0; hrow < 2; hrow++) {
                int rr = rowt + hrow * 8;
                if (rr >= M) continue;
                #pragma unroll
                for (int ni = 0; ni < 4; ni++) {
                    int col = cbase + ni * 8;
                    if ((N_ % 64 == 0) || (col + 1 < N_)) {
                        float v0 = acc[mi][ni][hrow * 2 + 0];
                        float v1 = acc[mi][ni][hrow * 2 + 1];
                        if (HAS_BIAS) {
                            v0 += __ldg(bias + col);
                            v1 += __ldg(bias + col + 1);
                        }
                        *(__half2*)(Z + (size_t)rr * N_ + col) = __floats2half2_rn(v0, v1);
                    }
                }
            }
        }
        __syncthreads();  // all warps done reading Bsm before next quarter load
    }
}

// ---------------- BN column stats + fused finalize (last-block pattern) -------
__global__ void k_colstats(const __half* __restrict__ Zl, double* __restrict__ sum,
                           double* __restrict__ sq, int M,
                           const float* __restrict__ gamma,
                           const float* __restrict__ beta,
                           float* __restrict__ scale, float* __restrict__ shift,
                           unsigned* __restrict__ cnt) {
    int c2 = threadIdx.x;  // 128 threads = 128 half2 column pairs
    int r0 = blockIdx.x * 512;
    int rend = min(r0 + 512, M);
    float s0 = 0.f, s1 = 0.f, q0 = 0.f, q1 = 0.f;
    const __half2* Z2 = (const __half2*)Zl;
    for (int r = r0; r < rend; r++) {
        float2 v = __half22float2(__ldg(Z2 + (size_t)r * 128 + c2));
        s0 += v.x;
        s1 += v.y;
        q0 = fmaf(v.x, v.x, q0);
        q1 = fmaf(v.y, v.y, q1);
    }
    atomicAdd(&sum[c2 * 2 + 0], (double)s0);
    atomicAdd(&sum[c2 * 2 + 1], (double)s1);
    atomicAdd(&sq[c2 * 2 + 0], (double)q0);
    atomicAdd(&sq[c2 * 2 + 1], (double)q1);

    __threadfence();
    __shared__ bool last;
    if (threadIdx.x == 0)
        last = (atomicAdd(cnt, 1u) == gridDim.x - 1);
    __syncthreads();
    if (last) {
        for (int i = threadIdx.x; i < 256; i += 128) {
            double mean = sum[i] / (double)NN;
            double var = sq[i] / (double)NN - mean * mean;
            float rstd = (float)(1.0 / sqrt(var + (double)EPS));
            float sc = rstd * __ldg(gamma + i);
            scale[i] = sc;
            shift[i] = __ldg(beta + i) - (float)mean * sc;
        }
    }
}

// ---------------- launch -----------------------------------------------------
extern "C" void kernel_launch(void* const* d_in, const int* in_sizes, int n_in,
                              void* d_out, int out_size) {
    const float* x      = (const float*)d_in[0];
    const int*   src    = (const int*)  d_in[1];
    const int*   dst    = (const int*)  d_in[2];
    const float* W1     = (const float*)d_in[3];
    const float* b1     = (const float*)d_in[4];
    const float* gamma1 = (const float*)d_in[5];
    const float* beta1  = (const float*)d_in[6];
    const float* W2     = (const float*)d_in[7];
    const float* b2     = (const float*)d_in[8];
    const float* gamma2 = (const float*)d_in[9];
    const float* beta2  = (const float*)d_in[10];
    const float* W3     = (const float*)d_in[11];
    const float* b3     = (const float*)d_in[12];
    float* out = (float*)d_out;
    int E = in_sizes[1];

    void *p_deg, *p_stats, *p_bnp, *p_h0, *p_h1, *p_h2, *p_cnt;
    void *p_agg1, *p_z1, *p_agg2, *p_z2, *p_xp;
    void *p_w1, *p_w2, *p_w3;
    cudaGetSymbolAddress(&p_deg,   g_deg);
    cudaGetSymbolAddress(&p_stats, g_stats);
    cudaGetSymbolAddress(&p_bnp,   g_bnp);
    cudaGetSymbolAddress(&p_h0,    g_h0);
    cudaGetSymbolAddress(&p_h1,    g_h1);
    cudaGetSymbolAddress(&p_h2,    g_h2);
    cudaGetSymbolAddress(&p_cnt,   g_cnt);
    cudaGetSymbolAddress(&p_agg1,  g_agg1);
    cudaGetSymbolAddress(&p_z1,    g_z1);
    cudaGetSymbolAddress(&p_agg2,  g_agg2);
    cudaGetSymbolAddress(&p_z2,    g_z2);
    cudaGetSymbolAddress(&p_xp,    g_xp);
    cudaGetSymbolAddress(&p_w1,    g_w1);
    cudaGetSymbolAddress(&p_w2,    g_w2);
    cudaGetSymbolAddress(&p_w3,    g_w3);

    const int SM1 = 192 * (128 + 8) * 2;  // 52224
    const int SM2 = 192 * (256 + 8) * 2;  // 101376
    const int SM3 = SM2;
    cudaFuncSetAttribute(k_gemm_mma<256, 128, true>,
                         cudaFuncAttributeMaxDynamicSharedMemorySize, SM1);
    cudaFuncSetAttribute(k_gemm_mma<256, 256, true>,
                         cudaFuncAttributeMaxDynamicSharedMemorySize, SM2);
    cudaFuncSetAttribute(k_gemm_mma<40, 256, false>,
                         cudaFuncAttributeMaxDynamicSharedMemorySize, SM3);

    cudaMemsetAsync(p_deg, 0, NN * sizeof(int), 0);
    cudaMemsetAsync(p_stats, 0, 4 * 256 * sizeof(double), 0);
    cudaMemsetAsync(p_cnt, 0, 2 * sizeof(unsigned), 0);

    const int T = 256;
    double* st = (double*)p_stats;
    float* bnp = (float*)p_bnp;
    unsigned* cnt = (unsigned*)p_cnt;
    int mg = (NN + 127) / 128;  // 782
    int csblk = (NN + 511) / 512;

    // W conversions (fused)
    k_wconv_all<<<(108544 + T - 1) / T, T>>>(W1, W2, W3);

    // CSR build + norms (norm fused into scan_c)
    k_hist<<<(E / 2 + T - 1) / T, T>>>(dst, E);
    k_scan_a<<<NBLK, 1024>>>();
    k_scan_c<<<NBLK, 1024>>>();
    k_fill<<<(E / 2 + T - 1) / T, T>>>(src, dst, E);

    // layer 1
    k_prep0<<<(NN * 64 + T - 1) / T, T>>>(x);
    k_gather<128><<<(NN + 15) / 16, T>>>((const __half*)p_h0, (__half*)p_agg1);
    k_gemm_mma<256, 128, true><<<mg, T, SM1>>>(
        (const __half*)p_agg1, b1, (const __half*)p_w1, (__half*)p_z1, NN);
    k_colstats<<<csblk, 128>>>((const __half*)p_z1, st, st + 256, NN,
                               gamma1, beta1, bnp, bnp + 256, cnt);
    k_prep<<<(NN * 128 + T - 1) / T, T>>>((const __half*)p_z1, bnp, bnp + 256,
                                          (__half*)p_h1);

    // layer 2
    k_gather<256><<<(NN + 7) / 8, T>>>((const __half*)p_h1, (__half*)p_agg2);
    k_gemm_mma<256, 256, true><<<mg, T, SM2>>>(
        (const __half*)p_agg2, b2, (const __half*)p_w2, (__half*)p_z2, NN);
    k_colstats<<<csblk, 128>>>((const __half*)p_z2, st + 512, st + 768, NN,
                               gamma2, beta2, bnp + 512, bnp + 768, cnt + 1);
    k_prep<<<(NN * 128 + T - 1) / T, T>>>((const __half*)p_z2, bnp + 512, bnp + 768,
                                          (__half*)p_h2);

    // layer 3: xp = h2 @ W3 (src-scaled), fused gather+log_softmax
    k_gemm_mma<40, 256, false><<<mg, T, SM3>>>(
        (const __half*)p_h2, nullptr, (const __half*)p_w3, (__half*)p_xp, NN);
    k_gather3_final<<<(NN + 31) / 32, T>>>(b3, out);
}

// round 17
// speedup vs baseline: 1.1805x; 1.0162x over previous
#include <cuda_runtime.h>
#include <cuda_fp16.h>
#include <math.h>
#include <stdint.h>

#define NN 100000
#define EPS 1e-5f
#define NBLK 98   // ceil(NN/1024)

// ---------------- scratch (static device globals) ----------------------------
__device__ int    g_deg[NN];
__device__ int    g_off[NN + 1];
__device__ int    g_cur[NN];
__device__ int    g_bsum[NBLK];
__device__ int    g_csr[3200000];
__device__ float  g_norm[NN];
__device__ unsigned g_cnt[4];   // [0],[1]: colstats last-block; [2]: scan spin
__device__ __align__(128) __half g_h0[NN * 128];    // x*norm, half
__device__ __align__(128) __half g_agg1[NN * 128];  // gathered, *norm_dst
__device__ __align__(128) __half g_z1[NN * 256];
__device__ __align__(128) __half g_h1[NN * 256];    // relu(bn(z1))*norm
__device__ __align__(128) __half g_agg2[NN * 256];
__device__ __align__(128) __half g_z2[NN * 256];
__device__ __align__(128) __half g_h2[NN * 256];    // relu(bn(z2))*norm
__device__ __align__(128) __half g_xp[NN * 40];     // h2 @ W3 (src-scaled)
__device__ double g_stats[4 * 256];
__device__ float  g_bnp[4 * 256];
__device__ __align__(128) __half g_w1[256 * 128];   // W1^T [N=256][K=128]
__device__ __align__(128) __half g_w2[256 * 256];   // W2^T
__device__ __align__(128) __half g_w3[40 * 256];    // W3^T [N=40][K=256]

// ---------------- smem addr / ldmatrix / mma helpers --------------------------
__device__ __forceinline__ uint32_t smem_u32(const void* p) {
    uint32_t a;
    asm("{ .reg .u64 t; cvta.to.shared.u64 t, %1; cvt.u32.u64 %0, t; }"
        : "=r"(a) : "l"(p));
    return a;
}

__device__ __forceinline__ void ldsm4(uint32_t* r, uint32_t addr) {
    asm volatile("ldmatrix.sync.aligned.m8n8.x4.shared.b16 {%0,%1,%2,%3}, [%4];"
                 : "=r"(r[0]), "=r"(r[1]), "=r"(r[2]), "=r"(r[3]) : "r"(addr));
}

__device__ __forceinline__ void mma16816(float* d, const uint32_t* a,
                                         const uint32_t* b, const float* c) {
    asm volatile(
        "mma.sync.aligned.m16n8k16.row.col.f32.f16.f16.f32 "
        "{%0,%1,%2,%3}, {%4,%5,%6,%7}, {%8,%9}, {%10,%11,%12,%13};"
        : "=f"(d[0]), "=f"(d[1]), "=f"(d[2]), "=f"(d[3])
        : "r"(a[0]), "r"(a[1]), "r"(a[2]), "r"(a[3]),
          "r"(b[0]), "r"(b[1]),
          "f"(c[0]), "f"(c[1]), "f"(c[2]), "f"(c[3]));
}

// ---------------- preamble: hist (blocks < hb) + W convert (blocks >= hb) -----
__global__ void k_pre(const int* __restrict__ dst, int E, int hb,
                      const float* __restrict__ W1, const float* __restrict__ W2,
                      const float* __restrict__ W3) {
    if (blockIdx.x < (unsigned)hb) {
        int i = blockIdx.x * 256 + threadIdx.x;
        int e = i * 2;
        if (e + 1 < E) {
            int2 d = __ldg((const int2*)dst + i);
            atomicAdd(&g_deg[d.x], 1);
            atomicAdd(&g_deg[d.y], 1);
        } else if (e < E) {
            atomicAdd(&g_deg[__ldg(dst + e)], 1);
        }
    } else {
        int i = (blockIdx.x - hb) * 256 + threadIdx.x;
        if (i < 32768) {                       // g_w1[n*128+k] = W1[k*256+n]
            int n = i >> 7, k = i & 127;
            g_w1[i] = __float2half(__ldg(W1 + k * 256 + n));
        } else if (i < 98304) {                // g_w2[n*256+k] = W2[k*256+n]
            int j = i - 32768;
            int n = j >> 8, k = j & 255;
            g_w2[j] = __float2half(__ldg(W2 + k * 256 + n));
        } else if (i < 108544) {               // g_w3[n*256+k] = W3[k*40+n]
            int j = i - 98304;
            int n = j >> 8, k = j & 255;
            g_w3[j] = __float2half(__ldg(W3 + k * 40 + n));
        }
    }
}

// ---------------- fused scan: block sums -> resident spin -> full scan --------
// 98 blocks of 1024 threads are always co-resident (98 < 148 SMs), so the
// arrival-counter spin cannot deadlock. Block 0 also zeroes g_stats.
__global__ void k_scan() {
    __shared__ int sh[1024];
    __shared__ int bs[128];
    __shared__ int ws[32];
    int tid = threadIdx.x;

    if (blockIdx.x == 0) ((double*)g_stats)[tid] = 0.0;  // 1024 doubles

    int i = blockIdx.x * 1024 + tid;
    int v = (i < NN) ? g_deg[i] : 0;
    sh[tid] = v;

    // block sum
    int w = v;
    #pragma unroll
    for (int o = 16; o; o >>= 1) w += __shfl_xor_sync(0xffffffffu, w, o);
    if ((tid & 31) == 0) ws[tid >> 5] = w;
    __syncthreads();
    if (tid < 32) {
        int u = ws[tid];
        #pragma unroll
        for (int o = 16; o; o >>= 1) u += __shfl_xor_sync(0xffffffffu, u, o);
        if (tid == 0) {
            g_bsum[blockIdx.x] = u;
            __threadfence();
            atomicAdd(&g_cnt[2], 1u);
        }
    }
    // spin until all block sums are posted
    if (tid == 0) {
        while (atomicAdd(&g_cnt[2], 0u) < (unsigned)NBLK) {}
    }
    __syncthreads();

    // scan block sums (L2-coherent reads; L1 has no stale line this launch)
    if (tid < 128) bs[tid] = (tid < NBLK) ? __ldcg(&g_bsum[tid]) : 0;
    __syncthreads();
    for (int o = 1; o < 128; o <<= 1) {
        int u = (tid < 128 && tid >= o) ? bs[tid - o] : 0;
        __syncthreads();
        if (tid < 128) bs[tid] += u;
        __syncthreads();
    }
    // local scan
    for (int o = 1; o < 1024; o <<= 1) {
        int u = (tid >= o) ? sh[tid - o] : 0;
        __syncthreads();
        sh[tid] += u;
        __syncthreads();
    }
    if (i < NN) {
        int base = blockIdx.x ? bs[blockIdx.x - 1] : 0;
        int ex = sh[tid] - v + base;
        g_off[i] = ex;
        g_cur[i] = ex;
        g_norm[i] = rsqrtf(fmaxf((float)v, 1.0f));
    }
    if (blockIdx.x == 0 && tid == 0) g_off[NN] = bs[NBLK - 1];
}

// ---------------- fused fill (blocks < fb) + prep0 (blocks >= fb) -------------
__global__ void k_fillprep(const int* __restrict__ src, const int* __restrict__ dst,
                           int E, int fb, const float* __restrict__ x) {
    if (blockIdx.x < (unsigned)fb) {
        int i = blockIdx.x * 256 + threadIdx.x;
        int e = i * 2;
        if (e + 1 < E) {
            int2 d = __ldg((const int2*)dst + i);
            int2 s = __ldg((const int2*)src + i);
            g_csr[atomicAdd(&g_cur[d.x], 1)] = s.x;
            g_csr[atomicAdd(&g_cur[d.y], 1)] = s.y;
        } else if (e < E) {
            g_csr[atomicAdd(&g_cur[__ldg(dst + e)], 1)] = __ldg(src + e);
        }
    } else {
        int t = (blockIdx.x - fb) * 256 + threadIdx.x;
        if (t >= NN * 64) return;
        int row = t >> 6;
        float n = g_norm[row];
        float2 v = __ldcs((const float2*)x + t);
        ((__half2*)g_h0)[t] = __floats2half2_rn(v.x * n, v.y * n);
    }
}

// z(half) -> h(half) = relu(z*sc+sh)*norm
__global__ void k_prep(const __half* __restrict__ Zl, const float* __restrict__ sc,
                       const float* __restrict__ sh, __half* __restrict__ Hh) {
    int t = blockIdx.x * blockDim.x + threadIdx.x;
    if (t >= NN * 128) return;
    int row = t >> 7, c2 = t & 127;
    float n = g_norm[row];
    float2 zf = __half22float2(__ldcs((const __half2*)Zl + t));
    float2 s2 = ((const float2*)sc)[c2];
    float2 h2 = ((const float2*)sh)[c2];
    float a = fmaxf(fmaf(zf.x, s2.x, h2.x), 0.f) * n;
    float b = fmaxf(fmaf(zf.y, s2.y, h2.y), 0.f) * n;
    ((__half2*)Hh)[t] = __floats2half2_rn(a, b);
}

// ---------------- CSR gathers (round-7 form, untouched: the measured optimum) -
__device__ __forceinline__ void add8(float* a, uint4 u) {
    __half2* h = (__half2*)&u;
    #pragma unroll
    for (int i = 0; i < 4; i++) {
        float2 f = __half22float2(h[i]);
        a[2 * i] += f.x;
        a[2 * i + 1] += f.y;
    }
}

template <int FEAT>
__global__ void k_gather(const __half* __restrict__ H, __half* __restrict__ OUT) {
    const int G = FEAT / 8;  // threads per node, 16B each
    int node = blockIdx.x * (256 / G) + threadIdx.x / G;
    int t = threadIdx.x % G;
    if (node >= NN) return;
    int beg = g_off[node], end = g_off[node + 1];
    const uint4* Hv = reinterpret_cast<const uint4*>(H);
    float acc[8] = {0, 0, 0, 0, 0, 0, 0, 0};
    int j = beg;
    for (; j + 8 <= end; j += 8) {
        int s[8];
        #pragma unroll
        for (int u = 0; u < 8; u++) s[u] = __ldg(g_csr + j + u);
        uint4 v[8];
        #pragma unroll
        for (int u = 0; u < 8; u++) v[u] = __ldg(Hv + (size_t)s[u] * G + t);
        #pragma unroll
        for (int u = 0; u < 8; u++) add8(acc, v[u]);
    }
    for (; j < end; j++) {
        int s = __ldg(g_csr + j);
        add8(acc, __ldg(Hv + (size_t)s * G + t));
    }
    float nd = g_norm[node];
    __half2 o[4];
    #pragma unroll
    for (int i = 0; i < 4; i++)
        o[i] = __floats2half2_rn(acc[2 * i] * nd, acc[2 * i + 1] * nd);
    __stcs(reinterpret_cast<float4*>(OUT) + (size_t)node * G + t, *(float4*)o);
}

// layer3 gather + log_softmax fused. 8 threads/node, t<5 hold 8 feats each.
__global__ void k_gather3_final(const float* __restrict__ b3, float* __restrict__ out) {
    int node = blockIdx.x * 32 + threadIdx.x / 8;
    int t = threadIdx.x & 7;
    int lane = threadIdx.x & 31;
    unsigned mask = 0xffu << (lane & ~7);
    if (node >= NN) return;
    float acc[8] = {0, 0, 0, 0, 0, 0, 0, 0};
    if (t < 5) {
        int beg = g_off[node], end = g_off[node + 1];
        const uint4* Hv = reinterpret_cast<const uint4*>(g_xp);  // 5 uint4/row
        int j = beg;
        for (; j + 8 <= end; j += 8) {
            int s[8];
            #pragma unroll
            for (int u = 0; u < 8; u++) s[u] = __ldg(g_csr + j + u);
            uint4 v[8];
            #pragma unroll
            for (int u = 0; u < 8; u++) v[u] = __ldg(Hv + (size_t)s[u] * 5 + t);
            #pragma unroll
            for (int u = 0; u < 8; u++) add8(acc, v[u]);
        }
        for (; j < end; j++) {
            int s = __ldg(g_csr + j);
            add8(acc, __ldg(Hv + (size_t)s * 5 + t));
        }
    }
    float nrm = g_norm[node];
    float v[8];
    float lm = -1e30f;
    if (t < 5) {
        #pragma unroll
        for (int i = 0; i < 8; i++) {
            v[i] = acc[i] * nrm + __ldg(b3 + t * 8 + i);
            lm = fmaxf(lm, v[i]);
        }
    }
    #pragma unroll
    for (int o = 4; o; o >>= 1) lm = fmaxf(lm, __shfl_xor_sync(mask, lm, o));
    float ls = 0.f;
    if (t < 5) {
        #pragma unroll
        for (int i = 0; i < 8; i++) ls += __expf(v[i] - lm);
    }
    #pragma unroll
    for (int o = 4; o; o >>= 1) ls += __shfl_xor_sync(mask, ls, o);
    float lg = __logf(ls);
    if (t < 5) {
        float4 o0 = {v[0] - lm - lg, v[1] - lm - lg, v[2] - lm - lg, v[3] - lm - lg};
        float4 o1 = {v[4] - lm - lg, v[5] - lm - lg, v[6] - lm - lg, v[7] - lm - lg};
        float* op = out + (size_t)node * 40 + t * 8;
        *(float4*)op = o0;
        *(float4*)(op + 4) = o1;
    }
}

// ---------------- HMMA GEMM: Z[M,N_] = half(A[M,K_] @ Bt[N_,K_]^T + bias) ----
// CTA owns 128 rows x FULL N_: A tile loaded ONCE, loop over 64-wide N
// quarters reloading only the B quarter (saves 4x A re-read through L2).
// 8 warps (4M x 2N), warp 32x32 per quarter, mma.sync m16n8k16 f16->f32.
template <int N_, int K_, bool HAS_BIAS>
__global__ void __launch_bounds__(256) k_gemm_mma(
    const __half* __restrict__ A, const float* __restrict__ bias,
    const __half* __restrict__ Bh, __half* __restrict__ Z, int M) {
    constexpr int KA = K_ + 8;  // halfs per smem row (16B pad, conflict-free ldsm)
    constexpr int NQ = (N_ + 63) / 64;
    extern __shared__ __half sm[];
    __half* Asm = sm;                 // [128][KA]
    __half* Bsm = sm + 128 * KA;      // [64][KA]

    int tid = threadIdx.x;
    int wid = tid >> 5, lane = tid & 31;
    int m0 = blockIdx.x * 128;

    // load A tile once (zeros past M); single-use stream -> evict-first
    const uint4* Ag = (const uint4*)A;
    for (int i = tid; i < 128 * (K_ / 8); i += 256) {
        int r = i / (K_ / 8), u = i % (K_ / 8);
        uint4 v = make_uint4(0, 0, 0, 0);
        if (m0 + r < M) v = __ldcs(Ag + (size_t)(m0 + r) * (K_ / 8) + u);
        *(uint4*)(Asm + r * KA + u * 8) = v;
    }

    int wm = wid & 3, wn = wid >> 2;
    uint32_t a_base = smem_u32(Asm);
    uint32_t b_base = smem_u32(Bsm);

    int arow = wm * 32 + (lane & 15);
    int acol = (lane >> 4) * 8;
    int brow = wn * 32 + ((lane >> 4) ? 8 : 0) + (lane & 7);
    int bk = ((lane >> 3) & 1) * 8;
    int cb_off = wn * 32 + (lane & 3) * 2;

    const uint4* Bg = (const uint4*)Bh;

    #pragma unroll 1
    for (int nq = 0; nq < NQ; nq++) {
        int n0 = nq * 64;
        // load B quarter (zeros past N_); W is hot -> default caching
        for (int i = tid; i < 64 * (K_ / 8); i += 256) {
            int r = i / (K_ / 8), u = i % (K_ / 8);
            uint4 v = make_uint4(0, 0, 0, 0);
            if (n0 + r < N_) v = __ldg(Bg + (size_t)(n0 + r) * (K_ / 8) + u);
            *(uint4*)(Bsm + r * KA + u * 8) = v;
        }
        __syncthreads();

        float acc[2][4][4] = {};
        #pragma unroll 4
        for (int k0 = 0; k0 < K_; k0 += 16) {
            uint32_t a[2][4];
            #pragma unroll
            for (int mi = 0; mi < 2; mi++)
                ldsm4(a[mi], a_base + (uint32_t)(((arow + mi * 16) * KA + k0 + acol) * 2));
            uint32_t b[2][4];
            #pragma unroll
            for (int nqq = 0; nqq < 2; nqq++)
                ldsm4(b[nqq], b_base + (uint32_t)(((brow + nqq * 16) * KA + k0 + bk) * 2));
            #pragma unroll
            for (int mi = 0; mi < 2; mi++)
                #pragma unroll
                for (int ni = 0; ni < 4; ni++)
                    mma16816(acc[mi][ni], a[mi], &b[ni >> 1][(ni & 1) * 2], acc[mi][ni]);
        }

        // epilogue for this quarter
        int cbase = n0 + cb_off;
        #pragma unroll
        for (int mi = 0; mi < 2; mi++) {
            int rowt = m0 + wm * 32 + mi * 16 + (lane >> 2);
            #pragma unroll
            for (int hrow = 0; hrow < 2; hrow++) {
                int rr = rowt + hrow * 8;
                if (rr >= M) continue;
                #pragma unroll
                for (int ni = 0; ni < 4; ni++) {
                    int col = cbase + ni * 8;
                    if ((N_ % 64 == 0) || (col + 1 < N_)) {
                        float v0 = acc[mi][ni][hrow * 2 + 0];
                        float v1 = acc[mi][ni][hrow * 2 + 1];
                        if (HAS_BIAS) {
                            v0 += __ldg(bias + col);
                            v1 += __ldg(bias + col + 1);
                        }
                        *(__half2*)(Z + (size_t)rr * N_ + col) = __floats2half2_rn(v0, v1);
                    }
                }
            }
        }
        __syncthreads();  // all warps done reading Bsm before next quarter load
    }
}

// ---------------- BN column stats + fused finalize (last-block pattern) -------
__global__ void k_colstats(const __half* __restrict__ Zl, double* __restrict__ sum,
                           double* __restrict__ sq, int M,
                           const float* __restrict__ gamma,
                           const float* __restrict__ beta,
                           float* __restrict__ scale, float* __restrict__ shift,
                           unsigned* __restrict__ cnt) {
    int c2 = threadIdx.x;  // 128 threads = 128 half2 column pairs
    int r0 = blockIdx.x * 512;
    int rend = min(r0 + 512, M);
    float s0 = 0.f, s1 = 0.f, q0 = 0.f, q1 = 0.f;
    const __half2* Z2 = (const __half2*)Zl;
    for (int r = r0; r < rend; r++) {
        float2 v = __half22float2(__ldg(Z2 + (size_t)r * 128 + c2));
        s0 += v.x;
        s1 += v.y;
        q0 = fmaf(v.x, v.x, q0);
        q1 = fmaf(v.y, v.y, q1);
    }
    atomicAdd(&sum[c2 * 2 + 0], (double)s0);
    atomicAdd(&sum[c2 * 2 + 1], (double)s1);
    atomicAdd(&sq[c2 * 2 + 0], (double)q0);
    atomicAdd(&sq[c2 * 2 + 1], (double)q1);

    __threadfence();
    __shared__ bool last;
    if (threadIdx.x == 0)
        last = (atomicAdd(cnt, 1u) == gridDim.x - 1);
    __syncthreads();
    if (last) {
        for (int i = threadIdx.x; i < 256; i += 128) {
            double mean = sum[i] / (double)NN;
            double var = sq[i] / (double)NN - mean * mean;
            float rstd = (float)(1.0 / sqrt(var + (double)EPS));
            float sc = rstd * __ldg(gamma + i);
            scale[i] = sc;
            shift[i] = __ldg(beta + i) - (float)mean * sc;
        }
    }
}

// ---------------- launch -----------------------------------------------------
extern "C" void kernel_launch(void* const* d_in, const int* in_sizes, int n_in,
                              void* d_out, int out_size) {
    const float* x      = (const float*)d_in[0];
    const int*   src    = (const int*)  d_in[1];
    const int*   dst    = (const int*)  d_in[2];
    const float* W1     = (const float*)d_in[3];
    const float* b1     = (const float*)d_in[4];
    const float* gamma1 = (const float*)d_in[5];
    const float* beta1  = (const float*)d_in[6];
    const float* W2     = (const float*)d_in[7];
    const float* b2     = (const float*)d_in[8];
    const float* gamma2 = (const float*)d_in[9];
    const float* beta2  = (const float*)d_in[10];
    const float* W3     = (const float*)d_in[11];
    const float* b3     = (const float*)d_in[12];
    float* out = (float*)d_out;
    int E = in_sizes[1];

    void *p_deg, *p_stats, *p_bnp, *p_h0, *p_h1, *p_h2, *p_cnt;
    void *p_agg1, *p_z1, *p_agg2, *p_z2, *p_xp;
    void *p_w1, *p_w2, *p_w3;
    cudaGetSymbolAddress(&p_deg,   g_deg);
    cudaGetSymbolAddress(&p_stats, g_stats);
    cudaGetSymbolAddress(&p_bnp,   g_bnp);
    cudaGetSymbolAddress(&p_h0,    g_h0);
    cudaGetSymbolAddress(&p_h1,    g_h1);
    cudaGetSymbolAddress(&p_h2,    g_h2);
    cudaGetSymbolAddress(&p_cnt,   g_cnt);
    cudaGetSymbolAddress(&p_agg1,  g_agg1);
    cudaGetSymbolAddress(&p_z1,    g_z1);
    cudaGetSymbolAddress(&p_agg2,  g_agg2);
    cudaGetSymbolAddress(&p_z2,    g_z2);
    cudaGetSymbolAddress(&p_xp,    g_xp);
    cudaGetSymbolAddress(&p_w1,    g_w1);
    cudaGetSymbolAddress(&p_w2,    g_w2);
    cudaGetSymbolAddress(&p_w3,    g_w3);

    const int SM1 = 192 * (128 + 8) * 2;  // 52224
    const int SM2 = 192 * (256 + 8) * 2;  // 101376
    const int SM3 = SM2;
    cudaFuncSetAttribute(k_gemm_mma<256, 128, true>,
                         cudaFuncAttributeMaxDynamicSharedMemorySize, SM1);
    cudaFuncSetAttribute(k_gemm_mma<256, 256, true>,
                         cudaFuncAttributeMaxDynamicSharedMemorySize, SM2);
    cudaFuncSetAttribute(k_gemm_mma<40, 256, false>,
                         cudaFuncAttributeMaxDynamicSharedMemorySize, SM3);

    cudaMemsetAsync(p_deg, 0, NN * sizeof(int), 0);
    cudaMemsetAsync(p_cnt, 0, 4 * sizeof(unsigned), 0);

    const int T = 256;
    double* st = (double*)p_stats;
    float* bnp = (float*)p_bnp;
    unsigned* cnt = (unsigned*)p_cnt;
    int mg = (NN + 127) / 128;  // 782
    int csblk = (NN + 511) / 512;

    // preamble: degree histogram + W conversions in one kernel
    int hb = (E / 2 + T - 1) / T;            // 6250
    int wb = (108544 + T - 1) / T;           // 424
    k_pre<<<hb + wb, T>>>(dst, E, hb, W1, W2, W3);

    // fused scan (also zeroes g_stats)
    k_scan<<<NBLK, 1024>>>();

    // fill CSR + prep0 in one kernel
    int fb = hb;                              // 6250
    int pb = (NN * 64 + T - 1) / T;          // 25000
    k_fillprep<<<fb + pb, T>>>(src, dst, E, fb, x);

    // layer 1
    k_gather<128><<<(NN + 15) / 16, T>>>((const __half*)p_h0, (__half*)p_agg1);
    k_gemm_mma<256, 128, true><<<mg, T, SM1>>>(
        (const __half*)p_agg1, b1, (const __half*)p_w1, (__half*)p_z1, NN);
    k_colstats<<<csblk, 128>>>((const __half*)p_z1, st, st + 256, NN,
                               gamma1, beta1, bnp, bnp + 256, cnt);
    k_prep<<<(NN * 128 + T - 1) / T, T>>>((const __half*)p_z1, bnp, bnp + 256,
                                          (__half*)p_h1);

    // layer 2
    k_gather<256><<<(NN + 7) / 8, T>>>((const __half*)p_h1, (__half*)p_agg2);
    k_gemm_mma<256, 256, true><<<mg, T, SM2>>>(
        (const __half*)p_agg2, b2, (const __half*)p_w2, (__half*)p_z2, NN);
    k_colstats<<<csblk, 128>>>((const __half*)p_z2, st + 512, st + 768, NN,
                               gamma2, beta2, bnp + 512, bnp + 768, cnt + 1);
    k_prep<<<(NN * 128 + T - 1) / T, T>>>((const __half*)p_z2, bnp + 512, bnp + 768,
                                          (__half*)p_h2);

    // layer 3: xp = h2 @ W3 (src-scaled), fused gather+log_softmax
    k_gemm_mma<40, 256, false><<<mg, T, SM3>>>(
        (const __half*)p_h2, nullptr, (const __half*)p_w3, (__half*)p_xp, NN);
    k_gather3_final<<<(NN + 31) / 32, T>>>(b3, out);
}